// round 1
// baseline (speedup 1.0000x reference)
#include <cuda_runtime.h>

// SimpleLSTM: B=4096, T=256, I=16, H=32, O=1 (fp32)
// out[b] = W_fc · h_T[b] + b_fc, LSTM gate order [i,f,g,o] (PyTorch).
//
// Strategy: warp-per-batch. Lane j owns hidden unit j:
//   - W_hh rows {j, 32+j, 64+j, 96+j} (4x32 fp32) cached in REGISTERS
//     (zero steady-state smem traffic for the recurrent matvec).
//   - W_ih in smem, layout [i][j*4+g] so each lane reads one float4
//     (consecutive 16B per lane -> conflict-free LDS.128).
//   - h broadcast per step: lane writes own h to smem, whole warp
//     re-reads the 32-float row as 8 broadcast LDS.128.
//   - activations: __expf (MUFU.EX2) + __fdividef (MUFU.RCP), ~1e-6 rel err.

#define BB 4096
#define TT 256
#define II 16
#define HH 32
#define WARPS_PER_BLK 4
#define THREADS (WARPS_PER_BLK * 32)

__device__ __forceinline__ float sigmoid_f(float v) {
    // 1/(1+exp(-v)) ; __expf -> MUFU.EX2, __fdividef -> MUFU.RCP
    return __fdividef(1.0f, 1.0f + __expf(-v));
}
__device__ __forceinline__ float tanh_f(float v) {
    // 1 - 2/(exp(2v)+1); saturates correctly via inf/0
    float e = __expf(2.0f * v);
    return 1.0f - __fdividef(2.0f, e + 1.0f);
}

__global__ void __launch_bounds__(THREADS, 2)
lstm_warp_kernel(const float* __restrict__ x,      // [B,T,I]
                 const float* __restrict__ W_ih,   // [4H,I]
                 const float* __restrict__ W_hh,   // [4H,H]
                 const float* __restrict__ b_ih,   // [4H]
                 const float* __restrict__ b_hh,   // [4H]
                 const float* __restrict__ W_fc,   // [1,H]
                 const float* __restrict__ b_fc,   // [1]
                 float* __restrict__ out)          // [B,1]
{
    __shared__ float wih_s[II][128];            // [i][j*4+g] = W_ih[(g*32+j)*16+i]
    __shared__ float bias_s[128];               // [j*4+g]    = b_ih[r]+b_hh[r]
    __shared__ float h_s[WARPS_PER_BLK][HH];    // per-warp hidden state

    const int tid  = threadIdx.x;
    const int wid  = tid >> 5;
    const int j    = tid & 31;
    const int b    = blockIdx.x * WARPS_PER_BLK + wid;

    // ---- stage shared weights (once per block) ----
    for (int idx = tid; idx < II * 128; idx += THREADS) {
        int i = idx >> 7;
        int r = idx & 127;        // r = j*4+g
        int jj = r >> 2, g = r & 3;
        wih_s[i][r] = W_ih[(g * HH + jj) * II + i];
    }
    for (int r = tid; r < 128; r += THREADS) {
        int jj = r >> 2, g = r & 3;
        bias_s[r] = b_ih[g * HH + jj] + b_hh[g * HH + jj];
    }
    __syncthreads();

    if (b >= BB) return;

    // ---- W_hh rows for this lane into registers (coalesced: each lane
    //      streams its own 128B row as 8 float4) ----
    float wg0[HH], wg1[HH], wg2[HH], wg3[HH];
    {
        const float4* whh4 = reinterpret_cast<const float4*>(W_hh);
        #pragma unroll
        for (int kk = 0; kk < 8; kk++) {
            float4 a0 = whh4[(0 * HH + j) * 8 + kk];
            float4 a1 = whh4[(1 * HH + j) * 8 + kk];
            float4 a2 = whh4[(2 * HH + j) * 8 + kk];
            float4 a3 = whh4[(3 * HH + j) * 8 + kk];
            wg0[4*kk+0] = a0.x; wg0[4*kk+1] = a0.y; wg0[4*kk+2] = a0.z; wg0[4*kk+3] = a0.w;
            wg1[4*kk+0] = a1.x; wg1[4*kk+1] = a1.y; wg1[4*kk+2] = a1.z; wg1[4*kk+3] = a1.w;
            wg2[4*kk+0] = a2.x; wg2[4*kk+1] = a2.y; wg2[4*kk+2] = a2.z; wg2[4*kk+3] = a2.w;
            wg3[4*kk+0] = a3.x; wg3[4*kk+1] = a3.y; wg3[4*kk+2] = a3.z; wg3[4*kk+3] = a3.w;
        }
    }

    const float4 bias_r = *reinterpret_cast<const float4*>(&bias_s[j * 4]);
    const float4* xrow  = reinterpret_cast<const float4*>(x + ((long)b * TT) * II);
    const float4* hrow4 = reinterpret_cast<const float4*>(&h_s[wid][0]);

    float h = 0.0f, c = 0.0f;

    #pragma unroll 1
    for (int t = 0; t < TT; t++) {
        // gates accumulator for lane's hidden unit: {i,f,g,o}
        float ai = bias_r.x, af = bias_r.y, ag = bias_r.z, ao = bias_r.w;

        // ---- input projection: x[b,t,:] (uniform across warp, 4x LDG.128) ----
        float4 x0 = xrow[t * 4 + 0];
        float4 x1 = xrow[t * 4 + 1];
        float4 x2 = xrow[t * 4 + 2];
        float4 x3 = xrow[t * 4 + 3];
        float xv[II] = {x0.x,x0.y,x0.z,x0.w, x1.x,x1.y,x1.z,x1.w,
                        x2.x,x2.y,x2.z,x2.w, x3.x,x3.y,x3.z,x3.w};
        #pragma unroll
        for (int i = 0; i < II; i++) {
            float4 w = *reinterpret_cast<const float4*>(&wih_s[i][j * 4]);
            ai = fmaf(w.x, xv[i], ai);
            af = fmaf(w.y, xv[i], af);
            ag = fmaf(w.z, xv[i], ag);
            ao = fmaf(w.w, xv[i], ao);
        }

        // ---- broadcast h across warp via smem ----
        h_s[wid][j] = h;
        __syncwarp();
        float hv[HH];
        #pragma unroll
        for (int kk = 0; kk < 8; kk++) {
            float4 hq = hrow4[kk];   // broadcast LDS.128 (all lanes same addr)
            hv[4*kk+0] = hq.x; hv[4*kk+1] = hq.y; hv[4*kk+2] = hq.z; hv[4*kk+3] = hq.w;
        }
        __syncwarp();

        // ---- recurrent matvec: weights from registers ----
        #pragma unroll
        for (int k = 0; k < HH; k++) {
            ai = fmaf(wg0[k], hv[k], ai);
            af = fmaf(wg1[k], hv[k], af);
            ag = fmaf(wg2[k], hv[k], ag);
            ao = fmaf(wg3[k], hv[k], ao);
        }

        // ---- activations + state update ----
        float ig = sigmoid_f(ai);
        float fg = sigmoid_f(af);
        float gg = tanh_f(ag);
        float og = sigmoid_f(ao);
        c = fmaf(fg, c, ig * gg);
        h = og * tanh_f(c);
    }

    // ---- final FC (O=1): warp reduction of h_j * W_fc[j] ----
    float v = h * W_fc[j];
    #pragma unroll
    for (int off = 16; off; off >>= 1)
        v += __shfl_xor_sync(0xffffffffu, v, off);
    if (j == 0)
        out[b] = v + b_fc[0];
}

extern "C" void kernel_launch(void* const* d_in, const int* in_sizes, int n_in,
                              void* d_out, int out_size) {
    (void)in_sizes; (void)n_in; (void)out_size;
    const float* x    = (const float*)d_in[0];
    const float* W_ih = (const float*)d_in[1];
    const float* W_hh = (const float*)d_in[2];
    const float* b_ih = (const float*)d_in[3];
    const float* b_hh = (const float*)d_in[4];
    const float* W_fc = (const float*)d_in[5];
    const float* b_fc = (const float*)d_in[6];
    float* out = (float*)d_out;

    dim3 grid(BB / WARPS_PER_BLK);   // 1024 blocks, warp per batch element
    dim3 block(THREADS);
    lstm_warp_kernel<<<grid, block>>>(x, W_ih, W_hh, b_ih, b_hh, W_fc, b_fc, out);
}

// round 2
// speedup vs baseline: 1.0996x; 1.0996x over previous
#include <cuda_runtime.h>

// SimpleLSTM: B=4096, T=256, I=16, H=32, O=1 (fp32)
// Warp-per-batch, lane j owns hidden unit j. f32x2-packed FFMA along the
// reduction dims (pairs come straight out of LDS.128/LDG.128, no packing ops).
// W_hh in registers (64 ull), W_ih in smem (conflict-free 16B/lane chunks),
// h broadcast via double-buffered smem row (1 syncwarp/step), x prefetched.

#define BB 4096
#define TT 256
#define II 16
#define HH 32
#define WARPS_PER_BLK 5
#define THREADS (WARPS_PER_BLK * 32)

typedef unsigned long long ull;

__device__ __forceinline__ void ffma2(ull& acc, ull a, ull b) {
    asm("fma.rn.f32x2 %0, %1, %2, %0;" : "+l"(acc) : "l"(a), "l"(b));
}
__device__ __forceinline__ float hadd2(ull v) {
    float lo, hi;
    asm("mov.b64 {%0, %1}, %2;" : "=f"(lo), "=f"(hi) : "l"(v));
    return lo + hi;
}
__device__ __forceinline__ ull pack2(float lo, float hi) {
    ull r;
    asm("mov.b64 %0, {%1, %2};" : "=l"(r) : "f"(lo), "f"(hi));
    return r;
}
__device__ __forceinline__ float sigmoid_f(float v) {
    return __fdividef(1.0f, 1.0f + __expf(-v));   // MUFU.EX2 + MUFU.RCP
}
__device__ __forceinline__ float tanh_f(float v) {
    float e = __expf(2.0f * v);
    return 1.0f - __fdividef(2.0f, e + 1.0f);
}

__global__ void __launch_bounds__(THREADS, 2)
lstm_warp_kernel(const float* __restrict__ x,      // [B,T,I]
                 const float* __restrict__ W_ih,   // [4H,I]
                 const float* __restrict__ W_hh,   // [4H,H]
                 const float* __restrict__ b_ih,   // [4H]
                 const float* __restrict__ b_hh,   // [4H]
                 const float* __restrict__ W_fc,   // [1,H]
                 const float* __restrict__ b_fc,   // [1]
                 float* __restrict__ out)          // [B,1]
{
    // wihA[i2][j] = {Wi[j][2i2],Wi[j][2i2+1], Wf[j][2i2],Wf[j][2i2+1]}
    // wihB[i2][j] = same for gates g,o. Lane j reads its own 16B -> conflict-free.
    __shared__ float4 wihA[II / 2][HH];
    __shared__ float4 wihB[II / 2][HH];
    __shared__ float  h_s[WARPS_PER_BLK][2][HH];   // double-buffered h broadcast

    const int tid = threadIdx.x;
    const int wid = tid / 32;
    const int j   = tid & 31;
    const int b   = blockIdx.x * WARPS_PER_BLK + wid;

    // ---- stage W_ih (once per block) ----
    for (int idx = tid; idx < (II / 2) * HH; idx += THREADS) {
        int i2 = idx >> 5, jj = idx & 31;
        wihA[i2][jj] = make_float4(W_ih[(0 * HH + jj) * II + 2 * i2],
                                   W_ih[(0 * HH + jj) * II + 2 * i2 + 1],
                                   W_ih[(1 * HH + jj) * II + 2 * i2],
                                   W_ih[(1 * HH + jj) * II + 2 * i2 + 1]);
        wihB[i2][jj] = make_float4(W_ih[(2 * HH + jj) * II + 2 * i2],
                                   W_ih[(2 * HH + jj) * II + 2 * i2 + 1],
                                   W_ih[(3 * HH + jj) * II + 2 * i2],
                                   W_ih[(3 * HH + jj) * II + 2 * i2 + 1]);
    }
    __syncthreads();

    if (b >= BB) return;

    // ---- W_hh rows for this lane's 4 gates as packed pairs (128 regs) ----
    ull whh2[4][HH / 2];
    {
        const ulonglong2* w4 = reinterpret_cast<const ulonglong2*>(W_hh);
        #pragma unroll
        for (int g = 0; g < 4; g++)
            #pragma unroll
            for (int kk = 0; kk < 8; kk++) {
                ulonglong2 q = w4[(g * HH + j) * 8 + kk];
                whh2[g][2 * kk + 0] = q.x;
                whh2[g][2 * kk + 1] = q.y;
            }
    }

    // ---- biases packed as (bias, 0) so acc init carries the bias ----
    ull biasp[4];
    #pragma unroll
    for (int g = 0; g < 4; g++)
        biasp[g] = pack2(b_ih[g * HH + j] + b_hh[g * HH + j], 0.0f);

    const ulonglong2* xrow = reinterpret_cast<const ulonglong2*>(x + (long)b * TT * II);
    const ulonglong2* wA   = reinterpret_cast<const ulonglong2*>(&wihA[0][j]);
    const ulonglong2* wB   = reinterpret_cast<const ulonglong2*>(&wihB[0][j]);

    float h = 0.0f, c = 0.0f;

    // prefetch x(t=0)
    ulonglong2 xq0 = xrow[0], xq1 = xrow[1], xq2 = xrow[2], xq3 = xrow[3];

    #pragma unroll 1
    for (int t = 0; t < TT; t++) {
        // issue next step's x loads early (latency hidden under this step)
        const int tn = (t + 1 < TT) ? t + 1 : t;
        ulonglong2 nq0 = xrow[tn * 4 + 0], nq1 = xrow[tn * 4 + 1];
        ulonglong2 nq2 = xrow[tn * 4 + 2], nq3 = xrow[tn * 4 + 3];

        // broadcast h (double-buffered: one syncwarp per step)
        const int buf = t & 1;
        h_s[wid][buf][j] = h;
        __syncwarp();

        ull ai = biasp[0], af = biasp[1], ag = biasp[2], ao = biasp[3];

        // ---- input projection: packed along i ----
        ull xp[8] = {xq0.x, xq0.y, xq1.x, xq1.y, xq2.x, xq2.y, xq3.x, xq3.y};
        #pragma unroll
        for (int i2 = 0; i2 < 8; i2++) {
            ulonglong2 a = wA[i2 * 32];   // (w_i pair, w_f pair)
            ulonglong2 bb = wB[i2 * 32];  // (w_g pair, w_o pair)
            ffma2(ai, a.x,  xp[i2]);
            ffma2(af, a.y,  xp[i2]);
            ffma2(ag, bb.x, xp[i2]);
            ffma2(ao, bb.y, xp[i2]);
        }

        // ---- recurrent matvec: packed along k, weights in registers ----
        const ulonglong2* hb = reinterpret_cast<const ulonglong2*>(&h_s[wid][buf][0]);
        #pragma unroll
        for (int kk = 0; kk < 8; kk++) {
            ulonglong2 hq = hb[kk];       // broadcast LDS.128 -> 2 packed pairs
            ffma2(ai, whh2[0][2 * kk], hq.x); ffma2(ai, whh2[0][2 * kk + 1], hq.y);
            ffma2(af, whh2[1][2 * kk], hq.x); ffma2(af, whh2[1][2 * kk + 1], hq.y);
            ffma2(ag, whh2[2][2 * kk], hq.x); ffma2(ag, whh2[2][2 * kk + 1], hq.y);
            ffma2(ao, whh2[3][2 * kk], hq.x); ffma2(ao, whh2[3][2 * kk + 1], hq.y);
        }

        // ---- horizontal add + activations + state update ----
        float gi = sigmoid_f(hadd2(ai));
        float gf = sigmoid_f(hadd2(af));
        float gg = tanh_f(hadd2(ag));
        float go = sigmoid_f(hadd2(ao));
        c = fmaf(gf, c, gi * gg);
        h = go * tanh_f(c);

        xq0 = nq0; xq1 = nq1; xq2 = nq2; xq3 = nq3;
    }

    // ---- final FC (O=1): warp reduction ----
    float v = h * W_fc[j];
    #pragma unroll
    for (int off = 16; off; off >>= 1)
        v += __shfl_xor_sync(0xffffffffu, v, off);
    if (j == 0)
        out[b] = v + b_fc[0];
}

extern "C" void kernel_launch(void* const* d_in, const int* in_sizes, int n_in,
                              void* d_out, int out_size) {
    (void)in_sizes; (void)n_in; (void)out_size;
    const float* x    = (const float*)d_in[0];
    const float* W_ih = (const float*)d_in[1];
    const float* W_hh = (const float*)d_in[2];
    const float* b_ih = (const float*)d_in[3];
    const float* b_hh = (const float*)d_in[4];
    const float* W_fc = (const float*)d_in[5];
    const float* b_fc = (const float*)d_in[6];
    float* out = (float*)d_out;

    dim3 grid((BB + WARPS_PER_BLK - 1) / WARPS_PER_BLK);   // 820 blocks
    dim3 block(THREADS);
    lstm_warp_kernel<<<grid, block>>>(x, W_ih, W_hh, b_ih, b_hh, W_fc, b_fc, out);
}

// round 3
// speedup vs baseline: 1.4052x; 1.2779x over previous
#include <cuda_runtime.h>

// SimpleLSTM: B=4096, T=256, I=16, H=32, O=1 (fp32)
// Warp handles TWO batch elements; lane j owns hidden unit j of both.
// W_hh (4x32 fp32 as 64 f32x2 pairs) in registers, SHARED by both batches.
// W_ih in smem, each LDS.128 feeds both batches. 8 independent FFMA2
// accumulation chains (4 gates x 2 batches) hide FFMA latency; the two
// batches' MUFU activation chains interleave.

#define BB 4096
#define TT 256
#define II 16
#define HH 32
#define WARPS_PER_BLK 4
#define THREADS (WARPS_PER_BLK * 32)

typedef unsigned long long ull;

__device__ __forceinline__ void ffma2(ull& acc, ull a, ull b) {
    asm("fma.rn.f32x2 %0, %1, %2, %0;" : "+l"(acc) : "l"(a), "l"(b));
}
__device__ __forceinline__ float hadd2(ull v) {
    float lo, hi;
    asm("mov.b64 {%0, %1}, %2;" : "=f"(lo), "=f"(hi) : "l"(v));
    return lo + hi;
}
__device__ __forceinline__ ull pack2(float lo, float hi) {
    ull r;
    asm("mov.b64 %0, {%1, %2};" : "=l"(r) : "f"(lo), "f"(hi));
    return r;
}
__device__ __forceinline__ float sigmoid_f(float v) {
    return __fdividef(1.0f, 1.0f + __expf(-v));   // MUFU.EX2 + MUFU.RCP
}
__device__ __forceinline__ float tanh_f(float v) {
    float e = __expf(2.0f * v);
    return 1.0f - __fdividef(2.0f, e + 1.0f);
}

__global__ void __launch_bounds__(THREADS, 2)
lstm_warp2_kernel(const float* __restrict__ x,      // [B,T,I]
                  const float* __restrict__ W_ih,   // [4H,I]
                  const float* __restrict__ W_hh,   // [4H,H]
                  const float* __restrict__ b_ih,   // [4H]
                  const float* __restrict__ b_hh,   // [4H]
                  const float* __restrict__ W_fc,   // [1,H]
                  const float* __restrict__ b_fc,   // [1]
                  float* __restrict__ out)          // [B,1]
{
    // wihA[i2][j] = {Wi[j][2i2..+1], Wf[j][2i2..+1]}, wihB same for g,o.
    __shared__ float4 wihA[II / 2][HH];
    __shared__ float4 wihB[II / 2][HH];
    __shared__ float  h_s[WARPS_PER_BLK][2][2][HH];  // [warp][buf][batch][j]

    const int tid = threadIdx.x;
    const int wid = tid >> 5;
    const int j   = tid & 31;
    const int b0  = (blockIdx.x * WARPS_PER_BLK + wid) * 2;   // batches b0, b0+1

    // ---- stage W_ih (once per block) ----
    for (int idx = tid; idx < (II / 2) * HH; idx += THREADS) {
        int i2 = idx >> 5, jj = idx & 31;
        wihA[i2][jj] = make_float4(W_ih[(0 * HH + jj) * II + 2 * i2],
                                   W_ih[(0 * HH + jj) * II + 2 * i2 + 1],
                                   W_ih[(1 * HH + jj) * II + 2 * i2],
                                   W_ih[(1 * HH + jj) * II + 2 * i2 + 1]);
        wihB[i2][jj] = make_float4(W_ih[(2 * HH + jj) * II + 2 * i2],
                                   W_ih[(2 * HH + jj) * II + 2 * i2 + 1],
                                   W_ih[(3 * HH + jj) * II + 2 * i2],
                                   W_ih[(3 * HH + jj) * II + 2 * i2 + 1]);
    }
    __syncthreads();

    // ---- W_hh rows for this lane's 4 gates as packed pairs (128 regs, shared) ----
    ull whh2[4][HH / 2];
    {
        const ulonglong2* w4 = reinterpret_cast<const ulonglong2*>(W_hh);
        #pragma unroll
        for (int g = 0; g < 4; g++)
            #pragma unroll
            for (int kk = 0; kk < 8; kk++) {
                ulonglong2 q = w4[(g * HH + j) * 8 + kk];
                whh2[g][2 * kk + 0] = q.x;
                whh2[g][2 * kk + 1] = q.y;
            }
    }

    ull biasp[4];
    #pragma unroll
    for (int g = 0; g < 4; g++)
        biasp[g] = pack2(b_ih[g * HH + j] + b_hh[g * HH + j], 0.0f);

    const ulonglong2* xr0 = reinterpret_cast<const ulonglong2*>(x + (long)(b0 + 0) * TT * II);
    const ulonglong2* xr1 = reinterpret_cast<const ulonglong2*>(x + (long)(b0 + 1) * TT * II);
    const ulonglong2* wA  = reinterpret_cast<const ulonglong2*>(&wihA[0][j]);
    const ulonglong2* wB  = reinterpret_cast<const ulonglong2*>(&wihB[0][j]);

    float h0 = 0.0f, c0 = 0.0f, h1 = 0.0f, c1 = 0.0f;

    // prefetch x(t=0) for both batches
    ulonglong2 xq0[4], xq1[4];
    #pragma unroll
    for (int q = 0; q < 4; q++) { xq0[q] = xr0[q]; xq1[q] = xr1[q]; }

    #pragma unroll 1
    for (int t = 0; t < TT; t++) {
        const int tn = (t + 1 < TT) ? t + 1 : t;
        ulonglong2 nq0[4], nq1[4];
        #pragma unroll
        for (int q = 0; q < 4; q++) { nq0[q] = xr0[tn * 4 + q]; nq1[q] = xr1[tn * 4 + q]; }

        // broadcast h for both batches (double-buffered)
        const int buf = t & 1;
        h_s[wid][buf][0][j] = h0;
        h_s[wid][buf][1][j] = h1;
        __syncwarp();

        ull ai0 = biasp[0], af0 = biasp[1], ag0 = biasp[2], ao0 = biasp[3];
        ull ai1 = biasp[0], af1 = biasp[1], ag1 = biasp[2], ao1 = biasp[3];

        // ---- input projection (one weight read feeds both batches) ----
        ull xp0[8] = {xq0[0].x, xq0[0].y, xq0[1].x, xq0[1].y,
                      xq0[2].x, xq0[2].y, xq0[3].x, xq0[3].y};
        ull xp1[8] = {xq1[0].x, xq1[0].y, xq1[1].x, xq1[1].y,
                      xq1[2].x, xq1[2].y, xq1[3].x, xq1[3].y};
        #pragma unroll
        for (int i2 = 0; i2 < 8; i2++) {
            ulonglong2 a  = wA[i2 * 32];
            ulonglong2 bb = wB[i2 * 32];
            ffma2(ai0, a.x,  xp0[i2]);  ffma2(ai1, a.x,  xp1[i2]);
            ffma2(af0, a.y,  xp0[i2]);  ffma2(af1, a.y,  xp1[i2]);
            ffma2(ag0, bb.x, xp0[i2]);  ffma2(ag1, bb.x, xp1[i2]);
            ffma2(ao0, bb.y, xp0[i2]);  ffma2(ao1, bb.y, xp1[i2]);
        }

        // ---- recurrent matvec: register weights, 8 independent chains ----
        const ulonglong2* hb0 = reinterpret_cast<const ulonglong2*>(&h_s[wid][buf][0][0]);
        const ulonglong2* hb1 = reinterpret_cast<const ulonglong2*>(&h_s[wid][buf][1][0]);
        #pragma unroll
        for (int kk = 0; kk < 8; kk++) {
            ulonglong2 hq0 = hb0[kk];   // broadcast LDS.128
            ulonglong2 hq1 = hb1[kk];
            ffma2(ai0, whh2[0][2*kk], hq0.x); ffma2(ai0, whh2[0][2*kk+1], hq0.y);
            ffma2(ai1, whh2[0][2*kk], hq1.x); ffma2(ai1, whh2[0][2*kk+1], hq1.y);
            ffma2(af0, whh2[1][2*kk], hq0.x); ffma2(af0, whh2[1][2*kk+1], hq0.y);
            ffma2(af1, whh2[1][2*kk], hq1.x); ffma2(af1, whh2[1][2*kk+1], hq1.y);
            ffma2(ag0, whh2[2][2*kk], hq0.x); ffma2(ag0, whh2[2][2*kk+1], hq0.y);
            ffma2(ag1, whh2[2][2*kk], hq1.x); ffma2(ag1, whh2[2][2*kk+1], hq1.y);
            ffma2(ao0, whh2[3][2*kk], hq0.x); ffma2(ao0, whh2[3][2*kk+1], hq0.y);
            ffma2(ao1, whh2[3][2*kk], hq1.x); ffma2(ao1, whh2[3][2*kk+1], hq1.y);
        }

        // ---- activations + state update (two interleaved MUFU chains) ----
        float gi0 = sigmoid_f(hadd2(ai0));
        float gi1 = sigmoid_f(hadd2(ai1));
        float gf0 = sigmoid_f(hadd2(af0));
        float gf1 = sigmoid_f(hadd2(af1));
        float gg0 = tanh_f(hadd2(ag0));
        float gg1 = tanh_f(hadd2(ag1));
        float go0 = sigmoid_f(hadd2(ao0));
        float go1 = sigmoid_f(hadd2(ao1));
        c0 = fmaf(gf0, c0, gi0 * gg0);
        c1 = fmaf(gf1, c1, gi1 * gg1);
        h0 = go0 * tanh_f(c0);
        h1 = go1 * tanh_f(c1);

        #pragma unroll
        for (int q = 0; q < 4; q++) { xq0[q] = nq0[q]; xq1[q] = nq1[q]; }
    }

    // ---- final FC (O=1): two warp reductions ----
    float wf = W_fc[j];
    float v0 = h0 * wf, v1 = h1 * wf;
    #pragma unroll
    for (int off = 16; off; off >>= 1) {
        v0 += __shfl_xor_sync(0xffffffffu, v0, off);
        v1 += __shfl_xor_sync(0xffffffffu, v1, off);
    }
    if (j == 0) {
        float bf = b_fc[0];
        out[b0 + 0] = v0 + bf;
        out[b0 + 1] = v1 + bf;
    }
}

extern "C" void kernel_launch(void* const* d_in, const int* in_sizes, int n_in,
                              void* d_out, int out_size) {
    (void)in_sizes; (void)n_in; (void)out_size;
    const float* x    = (const float*)d_in[0];
    const float* W_ih = (const float*)d_in[1];
    const float* W_hh = (const float*)d_in[2];
    const float* b_ih = (const float*)d_in[3];
    const float* b_hh = (const float*)d_in[4];
    const float* W_fc = (const float*)d_in[5];
    const float* b_fc = (const float*)d_in[6];
    float* out = (float*)d_out;

    dim3 grid(BB / (2 * WARPS_PER_BLK));   // 512 blocks, warp = 2 batches
    dim3 block(THREADS);
    lstm_warp2_kernel<<<grid, block>>>(x, W_ih, W_hh, b_ih, b_hh, W_fc, b_fc, out);
}

// round 4
// speedup vs baseline: 1.8924x; 1.3467x over previous
#include <cuda_runtime.h>

// SimpleLSTM: B=4096, T=256, I=16, H=32, O=1 (fp32)
// Warp = 4 batch elements; lane j owns hidden unit j of all 4.
// W_hh (4x32 fp32 = 64 f32x2 pairs) in registers, shared by 4 batches.
// 16 independent FFMA2 chains/warp. tanh.approx.f32 activations (MUFU.TANH).
// x staged smem via cp.async (1 LDGSTS/warp/step), h broadcast double-buffered.
// Grid 128 x 256thr, occ 1 -> single balanced wave.

#define BB 4096
#define TT 256
#define II 16
#define HH 32
#define WARPS_PER_BLK 8
#define THREADS (WARPS_PER_BLK * 32)
#define BPW 4   // batches per warp

typedef unsigned long long ull;

__device__ __forceinline__ void ffma2(ull& acc, ull a, ull b) {
    asm("fma.rn.f32x2 %0, %1, %2, %0;" : "+l"(acc) : "l"(a), "l"(b));
}
__device__ __forceinline__ float hadd2(ull v) {
    float lo, hi;
    asm("mov.b64 {%0, %1}, %2;" : "=f"(lo), "=f"(hi) : "l"(v));
    return lo + hi;
}
__device__ __forceinline__ ull pack2(float lo, float hi) {
    ull r;
    asm("mov.b64 %0, {%1, %2};" : "=l"(r) : "f"(lo), "f"(hi));
    return r;
}
__device__ __forceinline__ float tanh_a(float v) {
    float r;
    asm("tanh.approx.f32 %0, %1;" : "=f"(r) : "f"(v));   // MUFU.TANH
    return r;
}
__device__ __forceinline__ float sigmoid_a(float v) {
    return fmaf(tanh_a(0.5f * v), 0.5f, 0.5f);
}
__device__ __forceinline__ void cp_async16(void* smem_dst, const void* gsrc) {
    unsigned saddr = (unsigned)__cvta_generic_to_shared(smem_dst);
    asm volatile("cp.async.ca.shared.global [%0], [%1], 16;" :: "r"(saddr), "l"(gsrc));
}
__device__ __forceinline__ void cp_commit() {
    asm volatile("cp.async.commit_group;" ::: "memory");
}
__device__ __forceinline__ void cp_wait1() {
    asm volatile("cp.async.wait_group 1;" ::: "memory");
}

__global__ void __launch_bounds__(THREADS, 1)
lstm_warp4_kernel(const float* __restrict__ x,      // [B,T,I]
                  const float* __restrict__ W_ih,   // [4H,I]
                  const float* __restrict__ W_hh,   // [4H,H]
                  const float* __restrict__ b_ih,   // [4H]
                  const float* __restrict__ b_hh,   // [4H]
                  const float* __restrict__ W_fc,   // [1,H]
                  const float* __restrict__ b_fc,   // [1]
                  float* __restrict__ out)          // [B,1]
{
    // wihA[i2][j] = {Wi[j][2i2..+1], Wf[j][2i2..+1]}, wihB same for g,o.
    __shared__ float4 wihA[II / 2][HH];
    __shared__ float4 wihB[II / 2][HH];
    __shared__ float  h_s[WARPS_PER_BLK][2][BPW][HH];   // h broadcast, dbl-buffered
    __shared__ float  xs[WARPS_PER_BLK][2][BPW][II];    // x staging, dbl-buffered

    const int tid = threadIdx.x;
    const int wid = tid >> 5;
    const int j   = tid & 31;
    const int b0  = (blockIdx.x * WARPS_PER_BLK + wid) * BPW;

    // ---- stage W_ih (once per block) ----
    for (int idx = tid; idx < (II / 2) * HH; idx += THREADS) {
        int i2 = idx >> 5, jj = idx & 31;
        wihA[i2][jj] = make_float4(W_ih[(0 * HH + jj) * II + 2 * i2],
                                   W_ih[(0 * HH + jj) * II + 2 * i2 + 1],
                                   W_ih[(1 * HH + jj) * II + 2 * i2],
                                   W_ih[(1 * HH + jj) * II + 2 * i2 + 1]);
        wihB[i2][jj] = make_float4(W_ih[(2 * HH + jj) * II + 2 * i2],
                                   W_ih[(2 * HH + jj) * II + 2 * i2 + 1],
                                   W_ih[(3 * HH + jj) * II + 2 * i2],
                                   W_ih[(3 * HH + jj) * II + 2 * i2 + 1]);
    }
    __syncthreads();

    // ---- W_hh rows for this lane's 4 gates as packed pairs (128 regs, shared) ----
    ull whh2[4][HH / 2];
    {
        const ulonglong2* w4 = reinterpret_cast<const ulonglong2*>(W_hh);
        #pragma unroll
        for (int g = 0; g < 4; g++)
            #pragma unroll
            for (int kk = 0; kk < 8; kk++) {
                ulonglong2 q = w4[(g * HH + j) * 8 + kk];
                whh2[g][2 * kk + 0] = q.x;
                whh2[g][2 * kk + 1] = q.y;
            }
    }

    ull biasp[4];
    #pragma unroll
    for (int g = 0; g < 4; g++)
        biasp[g] = pack2(b_ih[g * HH + j] + b_hh[g * HH + j], 0.0f);

    const ulonglong2* wA = reinterpret_cast<const ulonglong2*>(&wihA[0][j]);
    const ulonglong2* wB = reinterpret_cast<const ulonglong2*>(&wihB[0][j]);

    // cp.async source for this lane (lanes 0..15: batch j>>2, 16B chunk j&3)
    const int cb = j >> 2, cc = j & 3;
    const float* gsrc = x + (long)(b0 + cb) * TT * II + cc * 4;

    float h[BPW] = {0.f, 0.f, 0.f, 0.f};
    float c[BPW] = {0.f, 0.f, 0.f, 0.f};

    // prefetch x(t=0) into buffer 0
    if (j < 16) cp_async16(&xs[wid][0][cb][cc * 4], gsrc);
    cp_commit();

    #pragma unroll 1
    for (int t = 0; t < TT; t++) {
        const int bufx = t & 1;

        // broadcast h (double-buffered)
        #pragma unroll
        for (int bb = 0; bb < BPW; bb++)
            h_s[wid][bufx][bb][j] = h[bb];

        // prefetch next x into other buffer (always commit to keep group count)
        const int tn = (t + 1 < TT) ? t + 1 : t;
        if (j < 16) cp_async16(&xs[wid][bufx ^ 1][cb][cc * 4], gsrc + tn * II);
        cp_commit();
        cp_wait1();          // current step's x resident
        __syncwarp();        // h + x visible warp-wide

        ull ai[BPW], af[BPW], ag[BPW], ao[BPW];
        #pragma unroll
        for (int bb = 0; bb < BPW; bb++) {
            ai[bb] = biasp[0]; af[bb] = biasp[1];
            ag[bb] = biasp[2]; ao[bb] = biasp[3];
        }

        // ---- load x pairs (broadcast LDS.128) ----
        ull xp[BPW][8];
        #pragma unroll
        for (int bb = 0; bb < BPW; bb++) {
            const ulonglong2* xs2 = reinterpret_cast<const ulonglong2*>(&xs[wid][bufx][bb][0]);
            ulonglong2 q0 = xs2[0], q1 = xs2[1], q2 = xs2[2], q3 = xs2[3];
            xp[bb][0] = q0.x; xp[bb][1] = q0.y; xp[bb][2] = q1.x; xp[bb][3] = q1.y;
            xp[bb][4] = q2.x; xp[bb][5] = q2.y; xp[bb][6] = q3.x; xp[bb][7] = q3.y;
        }

        // ---- input projection: one weight read feeds 4 batches ----
        #pragma unroll
        for (int i2 = 0; i2 < 8; i2++) {
            ulonglong2 a  = wA[i2 * 32];
            ulonglong2 w2 = wB[i2 * 32];
            #pragma unroll
            for (int bb = 0; bb < BPW; bb++) {
                ffma2(ai[bb], a.x,  xp[bb][i2]);
                ffma2(af[bb], a.y,  xp[bb][i2]);
                ffma2(ag[bb], w2.x, xp[bb][i2]);
                ffma2(ao[bb], w2.y, xp[bb][i2]);
            }
        }

        // ---- recurrent matvec: register weights, 16 independent chains ----
        #pragma unroll
        for (int kk = 0; kk < 8; kk++) {
            ulonglong2 hq[BPW];
            #pragma unroll
            for (int bb = 0; bb < BPW; bb++)
                hq[bb] = reinterpret_cast<const ulonglong2*>(&h_s[wid][bufx][bb][0])[kk];
            #pragma unroll
            for (int bb = 0; bb < BPW; bb++) {
                ffma2(ai[bb], whh2[0][2*kk], hq[bb].x); ffma2(ai[bb], whh2[0][2*kk+1], hq[bb].y);
                ffma2(af[bb], whh2[1][2*kk], hq[bb].x); ffma2(af[bb], whh2[1][2*kk+1], hq[bb].y);
                ffma2(ag[bb], whh2[2][2*kk], hq[bb].x); ffma2(ag[bb], whh2[2][2*kk+1], hq[bb].y);
                ffma2(ao[bb], whh2[3][2*kk], hq[bb].x); ffma2(ao[bb], whh2[3][2*kk+1], hq[bb].y);
            }
        }

        // ---- activations (MUFU.TANH) + state update ----
        #pragma unroll
        for (int bb = 0; bb < BPW; bb++) {
            float gi = sigmoid_a(hadd2(ai[bb]));
            float gf = sigmoid_a(hadd2(af[bb]));
            float gg = tanh_a(hadd2(ag[bb]));
            float go = sigmoid_a(hadd2(ao[bb]));
            c[bb] = fmaf(gf, c[bb], gi * gg);
            h[bb] = go * tanh_a(c[bb]);
        }
    }

    // ---- final FC (O=1): 4 warp reductions ----
    float wf = W_fc[j];
    float v[BPW];
    #pragma unroll
    for (int bb = 0; bb < BPW; bb++) v[bb] = h[bb] * wf;
    #pragma unroll
    for (int off = 16; off; off >>= 1) {
        #pragma unroll
        for (int bb = 0; bb < BPW; bb++)
            v[bb] += __shfl_xor_sync(0xffffffffu, v[bb], off);
    }
    if (j == 0) {
        float bf = b_fc[0];
        #pragma unroll
        for (int bb = 0; bb < BPW; bb++)
            out[b0 + bb] = v[bb] + bf;
    }
}

extern "C" void kernel_launch(void* const* d_in, const int* in_sizes, int n_in,
                              void* d_out, int out_size) {
    (void)in_sizes; (void)n_in; (void)out_size;
    const float* x    = (const float*)d_in[0];
    const float* W_ih = (const float*)d_in[1];
    const float* W_hh = (const float*)d_in[2];
    const float* b_ih = (const float*)d_in[3];
    const float* b_hh = (const float*)d_in[4];
    const float* W_fc = (const float*)d_in[5];
    const float* b_fc = (const float*)d_in[6];
    float* out = (float*)d_out;

    dim3 grid(BB / (BPW * WARPS_PER_BLK));   // 128 blocks, single wave
    dim3 block(THREADS);
    lstm_warp4_kernel<<<grid, block>>>(x, W_ih, W_hh, b_ih, b_hh, W_fc, b_fc, out);
}

// round 5
// speedup vs baseline: 1.8940x; 1.0008x over previous
#include <cuda_runtime.h>

// SimpleLSTM: B=4096, T=256, I=16, H=32, O=1 (fp32)
// Warp = 4 batch elements; lane j owns hidden unit j of all 4.
// W_hh (4x32 fp32 = 64 f32x2 pairs) in registers, shared by 4 batches.
// 16 independent FFMA2 chains/warp. tanh.approx.f32 activations (MUFU.TANH).
// x staged smem via cp.async (1 LDGSTS/warp/step), h broadcast double-buffered.
// Grid 128 x 256thr, occ 1 -> single balanced wave.

#define BB 4096
#define TT 256
#define II 16
#define HH 32
#define WARPS_PER_BLK 8
#define THREADS (WARPS_PER_BLK * 32)
#define BPW 4   // batches per warp

typedef unsigned long long ull;

__device__ __forceinline__ void ffma2(ull& acc, ull a, ull b) {
    asm("fma.rn.f32x2 %0, %1, %2, %0;" : "+l"(acc) : "l"(a), "l"(b));
}
__device__ __forceinline__ float hadd2(ull v) {
    float lo, hi;
    asm("mov.b64 {%0, %1}, %2;" : "=f"(lo), "=f"(hi) : "l"(v));
    return lo + hi;
}
__device__ __forceinline__ ull pack2(float lo, float hi) {
    ull r;
    asm("mov.b64 %0, {%1, %2};" : "=l"(r) : "f"(lo), "f"(hi));
    return r;
}
__device__ __forceinline__ float tanh_a(float v) {
    float r;
    asm("tanh.approx.f32 %0, %1;" : "=f"(r) : "f"(v));   // MUFU.TANH
    return r;
}
__device__ __forceinline__ float sigmoid_a(float v) {
    return fmaf(tanh_a(0.5f * v), 0.5f, 0.5f);
}
__device__ __forceinline__ void cp_async16(void* smem_dst, const void* gsrc) {
    unsigned saddr = (unsigned)__cvta_generic_to_shared(smem_dst);
    asm volatile("cp.async.ca.shared.global [%0], [%1], 16;" :: "r"(saddr), "l"(gsrc));
}
__device__ __forceinline__ void cp_commit() {
    asm volatile("cp.async.commit_group;" ::: "memory");
}
__device__ __forceinline__ void cp_wait1() {
    asm volatile("cp.async.wait_group 1;" ::: "memory");
}

__global__ void __launch_bounds__(THREADS, 1)
lstm_warp4_kernel(const float* __restrict__ x,      // [B,T,I]
                  const float* __restrict__ W_ih,   // [4H,I]
                  const float* __restrict__ W_hh,   // [4H,H]
                  const float* __restrict__ b_ih,   // [4H]
                  const float* __restrict__ b_hh,   // [4H]
                  const float* __restrict__ W_fc,   // [1,H]
                  const float* __restrict__ b_fc,   // [1]
                  float* __restrict__ out)          // [B,1]
{
    // wihA[i2][j] = {Wi[j][2i2..+1], Wf[j][2i2..+1]}, wihB same for g,o.
    __shared__ float4 wihA[II / 2][HH];
    __shared__ float4 wihB[II / 2][HH];
    __shared__ float  h_s[WARPS_PER_BLK][2][BPW][HH];   // h broadcast, dbl-buffered
    __shared__ float  xs[WARPS_PER_BLK][2][BPW][II];    // x staging, dbl-buffered

    const int tid = threadIdx.x;
    const int wid = tid >> 5;
    const int j   = tid & 31;
    const int b0  = (blockIdx.x * WARPS_PER_BLK + wid) * BPW;

    // ---- stage W_ih (once per block) ----
    for (int idx = tid; idx < (II / 2) * HH; idx += THREADS) {
        int i2 = idx >> 5, jj = idx & 31;
        wihA[i2][jj] = make_float4(W_ih[(0 * HH + jj) * II + 2 * i2],
                                   W_ih[(0 * HH + jj) * II + 2 * i2 + 1],
                                   W_ih[(1 * HH + jj) * II + 2 * i2],
                                   W_ih[(1 * HH + jj) * II + 2 * i2 + 1]);
        wihB[i2][jj] = make_float4(W_ih[(2 * HH + jj) * II + 2 * i2],
                                   W_ih[(2 * HH + jj) * II + 2 * i2 + 1],
                                   W_ih[(3 * HH + jj) * II + 2 * i2],
                                   W_ih[(3 * HH + jj) * II + 2 * i2 + 1]);
    }
    __syncthreads();

    // ---- W_hh rows for this lane's 4 gates as packed pairs (128 regs, shared) ----
    ull whh2[4][HH / 2];
    {
        const ulonglong2* w4 = reinterpret_cast<const ulonglong2*>(W_hh);
        #pragma unroll
        for (int g = 0; g < 4; g++)
            #pragma unroll
            for (int kk = 0; kk < 8; kk++) {
                ulonglong2 q = w4[(g * HH + j) * 8 + kk];
                whh2[g][2 * kk + 0] = q.x;
                whh2[g][2 * kk + 1] = q.y;
            }
    }

    ull biasp[4];
    #pragma unroll
    for (int g = 0; g < 4; g++)
        biasp[g] = pack2(b_ih[g * HH + j] + b_hh[g * HH + j], 0.0f);

    const ulonglong2* wA = reinterpret_cast<const ulonglong2*>(&wihA[0][j]);
    const ulonglong2* wB = reinterpret_cast<const ulonglong2*>(&wihB[0][j]);

    // cp.async source for this lane (lanes 0..15: batch j>>2, 16B chunk j&3)
    const int cb = j >> 2, cc = j & 3;
    const float* gsrc = x + (long)(b0 + cb) * TT * II + cc * 4;

    float h[BPW] = {0.f, 0.f, 0.f, 0.f};
    float c[BPW] = {0.f, 0.f, 0.f, 0.f};

    // prefetch x(t=0) into buffer 0
    if (j < 16) cp_async16(&xs[wid][0][cb][cc * 4], gsrc);
    cp_commit();

    #pragma unroll 1
    for (int t = 0; t < TT; t++) {
        const int bufx = t & 1;

        // broadcast h (double-buffered)
        #pragma unroll
        for (int bb = 0; bb < BPW; bb++)
            h_s[wid][bufx][bb][j] = h[bb];

        // prefetch next x into other buffer (always commit to keep group count)
        const int tn = (t + 1 < TT) ? t + 1 : t;
        if (j < 16) cp_async16(&xs[wid][bufx ^ 1][cb][cc * 4], gsrc + tn * II);
        cp_commit();
        cp_wait1();          // current step's x resident
        __syncwarp();        // h + x visible warp-wide

        ull ai[BPW], af[BPW], ag[BPW], ao[BPW];
        #pragma unroll
        for (int bb = 0; bb < BPW; bb++) {
            ai[bb] = biasp[0]; af[bb] = biasp[1];
            ag[bb] = biasp[2]; ao[bb] = biasp[3];
        }

        // ---- load x pairs (broadcast LDS.128) ----
        ull xp[BPW][8];
        #pragma unroll
        for (int bb = 0; bb < BPW; bb++) {
            const ulonglong2* xs2 = reinterpret_cast<const ulonglong2*>(&xs[wid][bufx][bb][0]);
            ulonglong2 q0 = xs2[0], q1 = xs2[1], q2 = xs2[2], q3 = xs2[3];
            xp[bb][0] = q0.x; xp[bb][1] = q0.y; xp[bb][2] = q1.x; xp[bb][3] = q1.y;
            xp[bb][4] = q2.x; xp[bb][5] = q2.y; xp[bb][6] = q3.x; xp[bb][7] = q3.y;
        }

        // ---- input projection: one weight read feeds 4 batches ----
        #pragma unroll
        for (int i2 = 0; i2 < 8; i2++) {
            ulonglong2 a  = wA[i2 * 32];
            ulonglong2 w2 = wB[i2 * 32];
            #pragma unroll
            for (int bb = 0; bb < BPW; bb++) {
                ffma2(ai[bb], a.x,  xp[bb][i2]);
                ffma2(af[bb], a.y,  xp[bb][i2]);
                ffma2(ag[bb], w2.x, xp[bb][i2]);
                ffma2(ao[bb], w2.y, xp[bb][i2]);
            }
        }

        // ---- recurrent matvec: register weights, 16 independent chains ----
        #pragma unroll
        for (int kk = 0; kk < 8; kk++) {
            ulonglong2 hq[BPW];
            #pragma unroll
            for (int bb = 0; bb < BPW; bb++)
                hq[bb] = reinterpret_cast<const ulonglong2*>(&h_s[wid][bufx][bb][0])[kk];
            #pragma unroll
            for (int bb = 0; bb < BPW; bb++) {
                ffma2(ai[bb], whh2[0][2*kk], hq[bb].x); ffma2(ai[bb], whh2[0][2*kk+1], hq[bb].y);
                ffma2(af[bb], whh2[1][2*kk], hq[bb].x); ffma2(af[bb], whh2[1][2*kk+1], hq[bb].y);
                ffma2(ag[bb], whh2[2][2*kk], hq[bb].x); ffma2(ag[bb], whh2[2][2*kk+1], hq[bb].y);
                ffma2(ao[bb], whh2[3][2*kk], hq[bb].x); ffma2(ao[bb], whh2[3][2*kk+1], hq[bb].y);
            }
        }

        // ---- activations (MUFU.TANH) + state update ----
        #pragma unroll
        for (int bb = 0; bb < BPW; bb++) {
            float gi = sigmoid_a(hadd2(ai[bb]));
            float gf = sigmoid_a(hadd2(af[bb]));
            float gg = tanh_a(hadd2(ag[bb]));
            float go = sigmoid_a(hadd2(ao[bb]));
            c[bb] = fmaf(gf, c[bb], gi * gg);
            h[bb] = go * tanh_a(c[bb]);
        }
    }

    // ---- final FC (O=1): 4 warp reductions ----
    float wf = W_fc[j];
    float v[BPW];
    #pragma unroll
    for (int bb = 0; bb < BPW; bb++) v[bb] = h[bb] * wf;
    #pragma unroll
    for (int off = 16; off; off >>= 1) {
        #pragma unroll
        for (int bb = 0; bb < BPW; bb++)
            v[bb] += __shfl_xor_sync(0xffffffffu, v[bb], off);
    }
    if (j == 0) {
        float bf = b_fc[0];
        #pragma unroll
        for (int bb = 0; bb < BPW; bb++)
            out[b0 + bb] = v[bb] + bf;
    }
}

extern "C" void kernel_launch(void* const* d_in, const int* in_sizes, int n_in,
                              void* d_out, int out_size) {
    (void)in_sizes; (void)n_in; (void)out_size;
    const float* x    = (const float*)d_in[0];
    const float* W_ih = (const float*)d_in[1];
    const float* W_hh = (const float*)d_in[2];
    const float* b_ih = (const float*)d_in[3];
    const float* b_hh = (const float*)d_in[4];
    const float* W_fc = (const float*)d_in[5];
    const float* b_fc = (const float*)d_in[6];
    float* out = (float*)d_out;

    dim3 grid(BB / (BPW * WARPS_PER_BLK));   // 128 blocks, single wave
    dim3 block(THREADS);
    lstm_warp4_kernel<<<grid, block>>>(x, W_ih, W_hh, b_ih, b_hh, W_fc, b_fc, out);
}